// round 16
// baseline (speedup 1.0000x reference)
#include <cuda_runtime.h>
#include <cuda_bf16.h>
#include <cuda_fp16.h>
#include <cstdint>

#define D 128
#define TMG 128             // rows per GEMM tile
#define XST 68              // smem row stride in 32-bit words
#define CAP 96              // edge bucket capacity (Poisson(32): P(>=96)~1e-20)
#define MAX_NODES 100000
#define MAX_EDGES 3200000

__device__ int      g_cnt[MAX_NODES];
__device__ float2   g_epack[(size_t)MAX_NODES * CAP];
// y and x2 stored as fp16x2 (64 words per 128-dim row), 25.6 MB each
__device__ uint32_t g_yh16[(size_t)MAX_NODES * 64];
__device__ uint32_t g_x2h16[(size_t)MAX_NODES * 64];
// fp16 W planes
__device__ uint32_t g_w16[2][128 * 64];

// smem word offsets: x plane + W0 + W1, each [128][XST]
#define OFF_X  0
#define OFF_W0 (128 * XST)
#define OFF_W1 (2 * 128 * XST)
#define SM_WORDS (3 * 128 * XST)          // 26112 words = 104448 B

__device__ __forceinline__ uint32_t pk_h2(float a, float b) {
    __half2 h = __floats2half2_rn(a, b);
    return *reinterpret_cast<uint32_t*>(&h);
}
__device__ __forceinline__ void cp_async16(uint32_t saddr, const void* gaddr) {
    asm volatile("cp.async.cg.shared.global [%0], [%1], 16;\n" :: "r"(saddr), "l"(gaddr));
}
__device__ __forceinline__ void cp_async_commit() {
    asm volatile("cp.async.commit_group;\n" ::: "memory");
}
__device__ __forceinline__ void cp_async_wait_all() {
    asm volatile("cp.async.wait_group 0;\n" ::: "memory");
}
__device__ __forceinline__ void mma16816h(float* c, const uint32_t* a,
                                          uint32_t b0, uint32_t b1) {
    asm volatile(
        "mma.sync.aligned.m16n8k16.row.col.f32.f16.f16.f32 "
        "{%0,%1,%2,%3}, {%4,%5,%6,%7}, {%8,%9}, {%0,%1,%2,%3};"
        : "+f"(c[0]), "+f"(c[1]), "+f"(c[2]), "+f"(c[3])
        : "r"(a[0]), "r"(a[1]), "r"(a[2]), "r"(a[3]), "r"(b0), "r"(b1));
}
__device__ __forceinline__ void ldsm_x4(uint32_t* r, uint32_t saddr) {
    asm volatile("ldmatrix.sync.aligned.m8n8.x4.shared.b16 {%0,%1,%2,%3}, [%4];"
                 : "=r"(r[0]), "=r"(r[1]), "=r"(r[2]), "=r"(r[3]) : "r"(saddr));
}

// ---------------------------------------------------------------------------
// Tiny one-time conversion: W0, W1 -> fp16 planes (x converted in-gemm)
// ---------------------------------------------------------------------------
__global__ void __launch_bounds__(256)
convert_kernel(const float* __restrict__ W0, const float* __restrict__ W1)
{
    int i = blockIdx.x * 256 + threadIdx.x;
    if (i >= 8192) return;
    int g = i >> 12;
    int j = i & 4095;
    float4 v = reinterpret_cast<const float4*>(g ? W1 : W0)[j];
    g_w16[g][j * 2]     = pk_h2(v.x, v.y);
    g_w16[g][j * 2 + 1] = pk_h2(v.z, v.w);
}

// ---------------------------------------------------------------------------
// Fused fp16 tensor-core GEMM: per 128-row tile computes BOTH
// y = xW0^T+b0 and x2 = xW1^T+b1, both stored fp16 (g_yh16 / g_x2h16).
// x tile converted fp32->fp16 in-kernel (LDG->cvt->STS).
// 104.4 KB smem, 2 CTAs/SM. 8 warps: warp_m = wid&3, warp_n = wid>>2.
// ---------------------------------------------------------------------------
__global__ void __launch_bounds__(256, 2)
mma_gemm(const float* __restrict__ x,
         const float* __restrict__ b0, const float* __restrict__ b1,
         int n_nodes)
{
    extern __shared__ uint32_t sm[];
    const int tid = threadIdx.x;
    const int m0  = blockIdx.x * TMG;

    uint32_t sb = (uint32_t)__cvta_generic_to_shared(sm);

    // ---- W planes via cp.async (issued first, overlaps x convert) ----
    #pragma unroll
    for (int q = 0; q < 16; ++q) {
        int i = tid + q * 256;
        int g = i >> 11;                 // 0 -> W0, 1 -> W1
        int r = (i & 2047) >> 4;
        int c = i & 15;
        cp_async16(sb + ((g ? OFF_W1 : OFF_W0) + r * XST + c * 4) * 4,
                   g_w16[g] + r * 64 + c * 4);
    }
    cp_async_commit();

    // ---- x tile: LDG fp32 float4 -> cvt -> STS fp16 (hides under W loads) ----
    #pragma unroll
    for (int q = 0; q < 16; ++q) {
        int i = tid + q * 256;           // 4096 float4
        int r = i >> 5;                  // row
        int c = i & 31;                  // float4 idx within row
        int node = m0 + r; if (node >= n_nodes) node = n_nodes - 1;
        float4 v = reinterpret_cast<const float4*>(x + (size_t)node * D)[c];
        sm[OFF_X + r * XST + c * 2]     = pk_h2(v.x, v.y);
        sm[OFF_X + r * XST + c * 2 + 1] = pk_h2(v.z, v.w);
    }

    cp_async_wait_all();
    __syncthreads();

    const int wid  = tid >> 5;
    const int lane = tid & 31;
    const int quad = lane >> 2;
    const int tq   = lane & 3;
    const int grp  = lane >> 3;
    const int rwi  = lane & 7;
    const int rowbase = (wid & 3) * 32;
    const int colbase = (wid >> 2) * 64;

    const uint32_t a0_base = sb + (OFF_X
                      + (rowbase + (grp & 1) * 8 + rwi) * XST + (grp >> 1) * 4) * 4;

    #pragma unroll
    for (int g = 0; g < 2; ++g) {
        float acc[2][8][4];
        #pragma unroll
        for (int i = 0; i < 2; ++i)
            #pragma unroll
            for (int j = 0; j < 8; ++j)
                #pragma unroll
                for (int c = 0; c < 4; ++c) acc[i][j][c] = 0.f;

        uint32_t a0 = a0_base;
        uint32_t a1 = a0 + 16 * XST * 4;
        uint32_t woff = g ? OFF_W1 : OFF_W0;
        uint32_t baddr[4];
        #pragma unroll
        for (int jp = 0; jp < 4; ++jp)
            baddr[jp] = sb + (woff
                        + (colbase + jp * 16 + ((grp >> 1) & 1) * 8 + rwi) * XST
                        + (grp & 1) * 4) * 4;

        #pragma unroll
        for (int kst = 0; kst < 8; ++kst) {
            uint32_t a[2][4];
            ldsm_x4(a[0], a0);  a0 += 32;
            ldsm_x4(a[1], a1);  a1 += 32;
            #pragma unroll
            for (int jp = 0; jp < 4; ++jp) {
                uint32_t bfr[4];
                ldsm_x4(bfr, baddr[jp]); baddr[jp] += 32;
                mma16816h(acc[0][2 * jp],     a[0], bfr[0], bfr[1]);
                mma16816h(acc[0][2 * jp + 1], a[0], bfr[2], bfr[3]);
                mma16816h(acc[1][2 * jp],     a[1], bfr[0], bfr[1]);
                mma16816h(acc[1][2 * jp + 1], a[1], bfr[2], bfr[3]);
            }
        }

        // ---- epilogue: +bias, store fp16 ----
        const float* bias = g ? b1 : b0;
        uint32_t* dst = g ? g_x2h16 : g_yh16;
        float2 bias2[8];
        #pragma unroll
        for (int j = 0; j < 8; ++j)
            bias2[j] = *reinterpret_cast<const float2*>(bias + colbase + j * 8 + tq * 2);

        #pragma unroll
        for (int i = 0; i < 2; ++i) {
            int r0 = m0 + rowbase + i * 16 + quad;
            int r1 = r0 + 8;
            #pragma unroll
            for (int j = 0; j < 8; ++j) {
                int wcol = (colbase + j * 8) / 2 + tq;
                if (r0 < n_nodes)
                    dst[(size_t)r0 * 64 + wcol] =
                        pk_h2(acc[i][j][0] + bias2[j].x, acc[i][j][1] + bias2[j].y);
                if (r1 < n_nodes)
                    dst[(size_t)r1 * 64 + wcol] =
                        pk_h2(acc[i][j][2] + bias2[j].x, acc[i][j][3] + bias2[j].y);
            }
        }
    }
}

// ---------------------------------------------------------------------------
// Bucketed scatter (no histogram, no scan)
// ---------------------------------------------------------------------------
__global__ void __launch_bounds__(256)
scatter_kernel(const int* __restrict__ erow, const int* __restrict__ ecol,
               const float* __restrict__ eval_, int n_edges)
{
    int i = blockIdx.x * blockDim.x + threadIdx.x;
    if (i >= n_edges) return;
    int r = erow[i];
    int p = atomicAdd(&g_cnt[r], 1);
    if (p < CAP)
        g_epack[(size_t)r * CAP + p] = make_float2(eval_[i], __int_as_float(ecol[i]));
}

// ---------------------------------------------------------------------------
// Gather: one warp per row; full 16-wide batches (zero-padded); fp16 y + x2;
// out write-only. out = relu(agg + x2).
// ---------------------------------------------------------------------------
__global__ void __launch_bounds__(256)
gather_kernel(float* __restrict__ out, int n_nodes)
{
    int row  = blockIdx.x * (blockDim.x >> 5) + (threadIdx.x >> 5);
    int lane = threadIdx.x & 31;
    if (row >= n_nodes) return;

    int deg = min(g_cnt[row], CAP);
    const float2* ep = g_epack + (size_t)row * CAP;

    float4 acc = make_float4(0.f, 0.f, 0.f, 0.f);

    for (int base = 0; base < deg; base += 32) {
        int idx = base + lane;
        float2 p = make_float2(0.f, 0.f);
        if (idx < deg) p = ep[idx];
        int cnt = min(32, deg - base);

        for (int j = 0; j < cnt; j += 16) {
            float v[16]; int c[16];
            #pragma unroll
            for (int u = 0; u < 16; ++u) {
                v[u] = __shfl_sync(0xffffffffu, p.x, j + u);
                c[u] = __float_as_int(__shfl_sync(0xffffffffu, p.y, j + u));
            }
            uint2 m[16];
            #pragma unroll
            for (int u = 0; u < 16; ++u)
                m[u] = reinterpret_cast<const uint2*>(g_yh16 + (size_t)c[u] * 64)[lane];
            #pragma unroll
            for (int u = 0; u < 16; ++u) {
                float2 lo = __half22float2(*reinterpret_cast<__half2*>(&m[u].x));
                float2 hi = __half22float2(*reinterpret_cast<__half2*>(&m[u].y));
                acc.x += v[u] * lo.x; acc.y += v[u] * lo.y;
                acc.z += v[u] * hi.x; acc.w += v[u] * hi.y;
            }
        }
    }

    uint2 x2w = reinterpret_cast<const uint2*>(g_x2h16 + (size_t)row * 64)[lane];
    float2 x2lo = __half22float2(*reinterpret_cast<__half2*>(&x2w.x));
    float2 x2hi = __half22float2(*reinterpret_cast<__half2*>(&x2w.y));

    float4 o;
    o.x = fmaxf(acc.x + x2lo.x, 0.f);
    o.y = fmaxf(acc.y + x2lo.y, 0.f);
    o.z = fmaxf(acc.z + x2hi.x, 0.f);
    o.w = fmaxf(acc.w + x2hi.y, 0.f);
    reinterpret_cast<float4*>(out + (size_t)row * D)[lane] = o;
}

extern "C" void kernel_launch(void* const* d_in, const int* in_sizes, int n_in,
                              void* d_out, int out_size)
{
    const float* x     = (const float*)d_in[0];
    const int*   erow  = (const int*)  d_in[1];
    const int*   ecol  = (const int*)  d_in[2];
    const float* eval_ = (const float*)d_in[3];
    const float* W     = (const float*)d_in[4];
    const float* b     = (const float*)d_in[5];
    const float* Wself = (const float*)d_in[6];
    const float* bself = (const float*)d_in[7];
    float* out = (float*)d_out;

    int n_nodes = in_sizes[0] / D;
    int n_edges = in_sizes[1];

    int* cntp;  cudaGetSymbolAddress((void**)&cntp, g_cnt);

    static cudaStream_t sB = nullptr;
    static cudaEvent_t  evFork = nullptr, evJoinB = nullptr;
    const int smem_bytes = SM_WORDS * 4;              // 104448
    if (!sB) {
        cudaStreamCreateWithFlags(&sB, cudaStreamNonBlocking);
        cudaEventCreateWithFlags(&evFork,  cudaEventDisableTiming);
        cudaEventCreateWithFlags(&evJoinB, cudaEventDisableTiming);
        cudaFuncSetAttribute(mma_gemm,
                             cudaFuncAttributeMaxDynamicSharedMemorySize, smem_bytes);
    }

    cudaEventRecord(evFork, 0);
    cudaStreamWaitEvent(sB, evFork, 0);

    // --- stream B: bucketed edge build ---
    cudaMemsetAsync(cntp, 0, (size_t)n_nodes * sizeof(int), sB);
    scatter_kernel<<<(n_edges + 255) / 256, 256, 0, sB>>>(erow, ecol, eval_, n_edges);
    cudaEventRecord(evJoinB, sB);

    // --- main stream: tiny W convert + fused tensor-core GEMM ---
    convert_kernel<<<32, 256>>>(W, Wself);

    int tiles = (n_nodes + TMG - 1) / TMG;
    mma_gemm<<<tiles, 256, smem_bytes>>>(x, b, bself, n_nodes);

    cudaStreamWaitEvent(0, evJoinB, 0);
    int warps_per_block = 256 / 32;
    int gblocks = (n_nodes + warps_per_block - 1) / warps_per_block;
    gather_kernel<<<gblocks, 256>>>(out, n_nodes);
}

// round 17
// speedup vs baseline: 1.1163x; 1.1163x over previous
#include <cuda_runtime.h>
#include <cuda_bf16.h>
#include <cuda_fp16.h>
#include <cstdint>

#define D 128
#define TMG 128             // rows per GEMM tile
#define XST 68              // smem row stride in 32-bit words
#define CAP 96              // edge bucket capacity (Poisson(32): P(>=96)~1e-20)
#define MAX_NODES 100000
#define MAX_EDGES 3200000

__device__ int      g_cnt[MAX_NODES];
__device__ float2   g_epack[(size_t)MAX_NODES * CAP + 16];  // +16 pad for unpredicated reads
// y and x2 stored as fp16x2 (64 words per 128-dim row)
__device__ uint32_t g_yh16[(size_t)MAX_NODES * 64];
__device__ uint32_t g_x2h16[(size_t)MAX_NODES * 64];
// fp16 operand planes
__device__ uint32_t g_x16[(size_t)MAX_NODES * 64];
__device__ uint32_t g_w16[2][128 * 64];

// smem word offsets: x plane + W0 + W1, each [128][XST]
#define OFF_X  0
#define OFF_W0 (128 * XST)
#define OFF_W1 (2 * 128 * XST)
#define SM_WORDS (3 * 128 * XST)          // 104448 B

__device__ __forceinline__ uint32_t pk_h2(float a, float b) {
    __half2 h = __floats2half2_rn(a, b);
    return *reinterpret_cast<uint32_t*>(&h);
}
__device__ __forceinline__ void cp_async16(uint32_t saddr, const void* gaddr) {
    asm volatile("cp.async.cg.shared.global [%0], [%1], 16;\n" :: "r"(saddr), "l"(gaddr));
}
__device__ __forceinline__ void cp_async_commit() {
    asm volatile("cp.async.commit_group;\n" ::: "memory");
}
__device__ __forceinline__ void cp_async_wait_all() {
    asm volatile("cp.async.wait_group 0;\n" ::: "memory");
}
__device__ __forceinline__ void mma16816h(float* c, const uint32_t* a,
                                          uint32_t b0, uint32_t b1) {
    asm volatile(
        "mma.sync.aligned.m16n8k16.row.col.f32.f16.f16.f32 "
        "{%0,%1,%2,%3}, {%4,%5,%6,%7}, {%8,%9}, {%0,%1,%2,%3};"
        : "+f"(c[0]), "+f"(c[1]), "+f"(c[2]), "+f"(c[3])
        : "r"(a[0]), "r"(a[1]), "r"(a[2]), "r"(a[3]), "r"(b0), "r"(b1));
}
__device__ __forceinline__ void ldsm_x4(uint32_t* r, uint32_t saddr) {
    asm volatile("ldmatrix.sync.aligned.m8n8.x4.shared.b16 {%0,%1,%2,%3}, [%4];"
                 : "=r"(r[0]), "=r"(r[1]), "=r"(r[2]), "=r"(r[3]) : "r"(saddr));
}

// ---------------------------------------------------------------------------
// One-time conversion: x, W0, W1 -> fp16 planes
// ---------------------------------------------------------------------------
__global__ void __launch_bounds__(256)
convert_kernel(const float* __restrict__ x,
               const float* __restrict__ W0, const float* __restrict__ W1,
               int n_nodes)
{
    int i = blockIdx.x * 256 + threadIdx.x;
    int nx = n_nodes * 32;

    const float4* src;
    uint32_t* dst;
    int j;
    if (i < nx)               { src = (const float4*)x;  j = i;            dst = g_x16;    }
    else if (i < nx + 4096)   { src = (const float4*)W0; j = i - nx;       dst = g_w16[0]; }
    else if (i < nx + 8192)   { src = (const float4*)W1; j = i - nx - 4096;dst = g_w16[1]; }
    else return;

    float4 v = src[j];
    dst[j * 2]     = pk_h2(v.x, v.y);
    dst[j * 2 + 1] = pk_h2(v.z, v.w);
}

// ---------------------------------------------------------------------------
// Fused fp16 tensor-core GEMM: per 128-row tile computes BOTH
// y = xW0^T+b0 -> g_yh16 (fp16) and x2 = xW1^T+b1 -> g_x2h16 (fp16),
// reusing the resident x plane. cp.async prologue. 2 CTAs/SM.
// ---------------------------------------------------------------------------
__global__ void __launch_bounds__(256, 2)
mma_gemm(const float* __restrict__ b0, const float* __restrict__ b1,
         int n_nodes)
{
    extern __shared__ uint32_t sm[];
    const int tid = threadIdx.x;
    const int m0  = blockIdx.x * TMG;

    uint32_t sb = (uint32_t)__cvta_generic_to_shared(sm);

    // ---- cp.async prologue: x plane + both W planes ----
    #pragma unroll
    for (int q = 0; q < 8; ++q) {
        int i = tid + q * 256;
        int r = i >> 4;
        int c = i & 15;
        int node = m0 + r; if (node >= n_nodes) node = n_nodes - 1;
        cp_async16(sb + (OFF_X + r * XST + c * 4) * 4,
                   g_x16 + (size_t)node * 64 + c * 4);
    }
    #pragma unroll
    for (int q = 0; q < 16; ++q) {
        int i = tid + q * 256;
        int g = i >> 11;
        int r = (i & 2047) >> 4;
        int c = i & 15;
        cp_async16(sb + ((g ? OFF_W1 : OFF_W0) + r * XST + c * 4) * 4,
                   g_w16[g] + r * 64 + c * 4);
    }
    cp_async_commit();
    cp_async_wait_all();
    __syncthreads();

    const int wid  = tid >> 5;
    const int lane = tid & 31;
    const int quad = lane >> 2;
    const int tq   = lane & 3;
    const int grp  = lane >> 3;
    const int rwi  = lane & 7;
    const int rowbase = (wid & 3) * 32;
    const int colbase = (wid >> 2) * 64;

    const uint32_t a0_base = sb + (OFF_X
                      + (rowbase + (grp & 1) * 8 + rwi) * XST + (grp >> 1) * 4) * 4;

    #pragma unroll
    for (int g = 0; g < 2; ++g) {
        float acc[2][8][4];
        #pragma unroll
        for (int i = 0; i < 2; ++i)
            #pragma unroll
            for (int j = 0; j < 8; ++j)
                #pragma unroll
                for (int c = 0; c < 4; ++c) acc[i][j][c] = 0.f;

        uint32_t a0 = a0_base;
        uint32_t a1 = a0 + 16 * XST * 4;
        uint32_t woff = g ? OFF_W1 : OFF_W0;
        uint32_t baddr[4];
        #pragma unroll
        for (int jp = 0; jp < 4; ++jp)
            baddr[jp] = sb + (woff
                        + (colbase + jp * 16 + ((grp >> 1) & 1) * 8 + rwi) * XST
                        + (grp & 1) * 4) * 4;

        #pragma unroll
        for (int kst = 0; kst < 8; ++kst) {
            uint32_t a[2][4];
            ldsm_x4(a[0], a0);  a0 += 32;
            ldsm_x4(a[1], a1);  a1 += 32;
            #pragma unroll
            for (int jp = 0; jp < 4; ++jp) {
                uint32_t bfr[4];
                ldsm_x4(bfr, baddr[jp]); baddr[jp] += 32;
                mma16816h(acc[0][2 * jp],     a[0], bfr[0], bfr[1]);
                mma16816h(acc[0][2 * jp + 1], a[0], bfr[2], bfr[3]);
                mma16816h(acc[1][2 * jp],     a[1], bfr[0], bfr[1]);
                mma16816h(acc[1][2 * jp + 1], a[1], bfr[2], bfr[3]);
            }
        }

        // ---- epilogue: +bias, store fp16 ----
        const float* bias = g ? b1 : b0;
        uint32_t* dst = g ? g_x2h16 : g_yh16;
        float2 bias2[8];
        #pragma unroll
        for (int j = 0; j < 8; ++j)
            bias2[j] = *reinterpret_cast<const float2*>(bias + colbase + j * 8 + tq * 2);

        #pragma unroll
        for (int i = 0; i < 2; ++i) {
            int r0 = m0 + rowbase + i * 16 + quad;
            int r1 = r0 + 8;
            #pragma unroll
            for (int j = 0; j < 8; ++j) {
                int wcol = (colbase + j * 8) / 2 + tq;
                if (r0 < n_nodes)
                    dst[(size_t)r0 * 64 + wcol] =
                        pk_h2(acc[i][j][0] + bias2[j].x, acc[i][j][1] + bias2[j].y);
                if (r1 < n_nodes)
                    dst[(size_t)r1 * 64 + wcol] =
                        pk_h2(acc[i][j][2] + bias2[j].x, acc[i][j][3] + bias2[j].y);
            }
        }
    }
}

// ---------------------------------------------------------------------------
// Bucketed scatter (no histogram, no scan)
// ---------------------------------------------------------------------------
__global__ void __launch_bounds__(256)
scatter_kernel(const int* __restrict__ erow, const int* __restrict__ ecol,
               const float* __restrict__ eval_, int n_edges)
{
    int i = blockIdx.x * blockDim.x + threadIdx.x;
    if (i >= n_edges) return;
    int r = erow[i];
    int p = atomicAdd(&g_cnt[r], 1);
    if (p < CAP)
        g_epack[(size_t)r * CAP + p] = make_float2(eval_[i], __int_as_float(ecol[i]));
}

// ---------------------------------------------------------------------------
// Gather: HALF-WARP per row (16 lanes x uint4 = 256B row), 2 rows per warp.
// Edge metadata via warp-uniform LDG.64 (no shuffles). 8 edges in flight.
// out = relu(agg + x2), write-only out.
// ---------------------------------------------------------------------------
__global__ void __launch_bounds__(256)
gather_kernel(float* __restrict__ out, int n_nodes)
{
    int warp = blockIdx.x * 8 + (threadIdx.x >> 5);
    int lane = threadIdx.x & 31;
    int half = lane >> 4;
    int hl   = lane & 15;

    int row = warp * 2 + half;
    if (warp * 2 >= n_nodes) return;
    bool rowok = row < n_nodes;
    int rrow = rowok ? row : (n_nodes - 1);

    int deg = rowok ? min(g_cnt[rrow], CAP) : 0;
    const float2* ep = g_epack + (size_t)rrow * CAP;

    // warp-uniform loop bound = max(deg of the two halves)
    int dmax = max(deg, __shfl_xor_sync(0xffffffffu, deg, 16));

    float acc[8];
    #pragma unroll
    for (int k = 0; k < 8; ++k) acc[k] = 0.f;

    for (int j = 0; j < dmax; j += 8) {
        float v[8]; int c[8];
        #pragma unroll
        for (int u = 0; u < 8; ++u) {
            float2 e = ep[j + u];             // uniform per half; padded buffer
            bool ok = (j + u) < deg;
            v[u] = ok ? e.x : 0.f;
            c[u] = ok ? __float_as_int(e.y) : 0;
        }
        uint4 m[8];
        #pragma unroll
        for (int u = 0; u < 8; ++u)
            m[u] = *reinterpret_cast<const uint4*>(
                       g_yh16 + (size_t)c[u] * 64 + hl * 4);
        #pragma unroll
        for (int u = 0; u < 8; ++u) {
            float2 f0 = __half22float2(*reinterpret_cast<__half2*>(&m[u].x));
            float2 f1 = __half22float2(*reinterpret_cast<__half2*>(&m[u].y));
            float2 f2 = __half22float2(*reinterpret_cast<__half2*>(&m[u].z));
            float2 f3 = __half22float2(*reinterpret_cast<__half2*>(&m[u].w));
            acc[0] += v[u] * f0.x; acc[1] += v[u] * f0.y;
            acc[2] += v[u] * f1.x; acc[3] += v[u] * f1.y;
            acc[4] += v[u] * f2.x; acc[5] += v[u] * f2.y;
            acc[6] += v[u] * f3.x; acc[7] += v[u] * f3.y;
        }
    }

    if (!rowok) return;

    uint4 x2w = *reinterpret_cast<const uint4*>(g_x2h16 + (size_t)row * 64 + hl * 4);
    float2 s0 = __half22float2(*reinterpret_cast<__half2*>(&x2w.x));
    float2 s1 = __half22float2(*reinterpret_cast<__half2*>(&x2w.y));
    float2 s2 = __half22float2(*reinterpret_cast<__half2*>(&x2w.z));
    float2 s3 = __half22float2(*reinterpret_cast<__half2*>(&x2w.w));

    float4 o0, o1;
    o0.x = fmaxf(acc[0] + s0.x, 0.f);
    o0.y = fmaxf(acc[1] + s0.y, 0.f);
    o0.z = fmaxf(acc[2] + s1.x, 0.f);
    o0.w = fmaxf(acc[3] + s1.y, 0.f);
    o1.x = fmaxf(acc[4] + s2.x, 0.f);
    o1.y = fmaxf(acc[5] + s2.y, 0.f);
    o1.z = fmaxf(acc[6] + s3.x, 0.f);
    o1.w = fmaxf(acc[7] + s3.y, 0.f);

    float4* op = reinterpret_cast<float4*>(out + (size_t)row * D + hl * 8);
    op[0] = o0;
    op[1] = o1;
}

extern "C" void kernel_launch(void* const* d_in, const int* in_sizes, int n_in,
                              void* d_out, int out_size)
{
    const float* x     = (const float*)d_in[0];
    const int*   erow  = (const int*)  d_in[1];
    const int*   ecol  = (const int*)  d_in[2];
    const float* eval_ = (const float*)d_in[3];
    const float* W     = (const float*)d_in[4];
    const float* b     = (const float*)d_in[5];
    const float* Wself = (const float*)d_in[6];
    const float* bself = (const float*)d_in[7];
    float* out = (float*)d_out;

    int n_nodes = in_sizes[0] / D;
    int n_edges = in_sizes[1];

    int* cntp;  cudaGetSymbolAddress((void**)&cntp, g_cnt);

    static cudaStream_t sB = nullptr;
    static cudaEvent_t  evFork = nullptr, evJoinB = nullptr;
    const int smem_bytes = SM_WORDS * 4;              // 104448
    if (!sB) {
        cudaStreamCreateWithFlags(&sB, cudaStreamNonBlocking);
        cudaEventCreateWithFlags(&evFork,  cudaEventDisableTiming);
        cudaEventCreateWithFlags(&evJoinB, cudaEventDisableTiming);
        cudaFuncSetAttribute(mma_gemm,
                             cudaFuncAttributeMaxDynamicSharedMemorySize, smem_bytes);
    }

    cudaEventRecord(evFork, 0);
    cudaStreamWaitEvent(sB, evFork, 0);

    // --- stream B: bucketed edge build ---
    cudaMemsetAsync(cntp, 0, (size_t)n_nodes * sizeof(int), sB);
    scatter_kernel<<<(n_edges + 255) / 256, 256, 0, sB>>>(erow, ecol, eval_, n_edges);
    cudaEventRecord(evJoinB, sB);

    // --- main stream: convert + fused tensor-core GEMM ---
    int conv_total = n_nodes * 32 + 8192;
    convert_kernel<<<(conv_total + 255) / 256, 256>>>(x, W, Wself, n_nodes);

    int tiles = (n_nodes + TMG - 1) / TMG;
    mma_gemm<<<tiles, 256, smem_bytes>>>(b, bself, n_nodes);

    cudaStreamWaitEvent(0, evJoinB, 0);
    // 2 rows per warp, 8 warps per block -> 16 rows per block
    int gblocks = (n_nodes + 15) / 16;
    gather_kernel<<<gblocks, 256>>>(out, n_nodes);
}